// round 10
// baseline (speedup 1.0000x reference)
#include <cuda_runtime.h>
#include <cuda_bf16.h>
#include <math.h>
#include <stdint.h>

#define NMAT 4
#define NSUB 4096
#define DIM 64
#define KTOP 20
#define NROWS 8192
#define DELTA 0.008f
#define FULLM 0xffffffffu
#define CAND 48            // candidates per half-row

// device global scratch (no allocation allowed)
__device__ float g_v1[NMAT][NSUB][DIM];
__device__ float g_v2[NMAT][NSUB][DIM];
__device__ __nv_bfloat16 g_v1b[NMAT][NSUB][DIM];
__device__ __nv_bfloat16 g_v2b[NMAT][NSUB][DIM];
__device__ float          g_cm[NROWS][256];       // per-row 32-col sub-chunk maxima
__device__ float          g_T[NROWS];             // per-row filter threshold
__device__ float          g_cval[NROWS][2 * CAND];
__device__ unsigned short g_ccol[NROWS][2 * CAND];

__device__ __forceinline__ uint32_t smem_u32(const void* p) {
    uint32_t a;
    asm("{ .reg .u64 t; cvta.to.shared.u64 t, %1; cvt.u32.u64 %0, t; }" : "=r"(a) : "l"(p));
    return a;
}

// ---------------------------------------------------------------------------
// v = emb @ w + b (fp32) + bf16 copy
// ---------------------------------------------------------------------------
__global__ void compute_v_kernel(const float* __restrict__ emb1,
                                 const float* __restrict__ emb2,
                                 const float* __restrict__ w1,
                                 const float* __restrict__ w2,
                                 const float* __restrict__ b1,
                                 const float* __restrict__ b2) {
    int which = blockIdx.z;
    int k = blockIdx.y;
    int tile = blockIdx.x;
    const float* emb = which ? emb2 : emb1;
    const float* w   = which ? w2   : w1;
    const float* b   = which ? b2   : b1;
    float* vout            = which ? &g_v2[0][0][0]  : &g_v1[0][0][0];
    __nv_bfloat16* voutb   = which ? &g_v2b[0][0][0] : &g_v1b[0][0][0];

    __shared__ float semb[64 * 65];
    __shared__ float sw[64 * 64];
    __shared__ float sb[64];

    int tid = threadIdx.x;
    for (int t = tid; t < 4096; t += 256) {
        int r = t >> 6, e = t & 63;
        semb[r * 65 + e] = emb[(size_t)(k * NSUB + tile * 64 + r) * 64 + e];
        sw[t] = w[k * 4096 + t];
    }
    if (tid < 64) sb[tid] = b[k * 64 + tid];
    __syncthreads();

    int nl = tid & 63, q = tid >> 6;
    float acc[16];
#pragma unroll
    for (int d = 0; d < 16; d++) acc[d] = 0.f;

#pragma unroll 4
    for (int e = 0; e < 64; e++) {
        float a = semb[nl * 65 + e];
#pragma unroll
        for (int jj = 0; jj < 4; jj++) {
            float4 wv = *(const float4*)&sw[e * 64 + q * 16 + jj * 4];
            acc[jj * 4 + 0] += a * wv.x;
            acc[jj * 4 + 1] += a * wv.y;
            acc[jj * 4 + 2] += a * wv.z;
            acc[jj * 4 + 3] += a * wv.w;
        }
    }

    size_t rowoff = (size_t)(k * NSUB + tile * 64 + nl) * 64;
    float* orow = vout + rowoff;
    __nv_bfloat16* orowb = voutb + rowoff;
#pragma unroll
    for (int dd = 0; dd < 16; dd++) {
        int d = q * 16 + dd;
        float v = acc[dd] + sb[d];
        orow[d]  = v;
        orowb[d] = __float2bfloat16(v);
    }
}

// ---------------------------------------------------------------------------
// HMMA plumbing. 256 threads, 64-row tile: warp w = (rowband rb = w&3) x
// (colhalf ch = w>>2). Warp computes 16 rows x 32 cols per 64-col chunk.
// B fragments via ldmatrix.x4 (4 mats = 2 k-steps per instruction).
// ---------------------------------------------------------------------------
#define OFF_A  0
#define OFF_B  9216
#define SM_AB  27648            // A(9216) + 2 B buffers(2x9216)

#define MMA_CHUNK4(acc, af, bbuf, ch, lane)                                     \
    do {                                                                        \
        uint32_t baddr0 = (bbuf) + ((ch) * 32 + ((lane) & 7)) * 144             \
                          + ((lane) >> 3) * 16;                                 \
        _Pragma("unroll")                                                       \
        for (int nt = 0; nt < 4; nt++) {                                        \
            uint32_t ba = baddr0 + nt * 8 * 144;                                \
            uint32_t b0, b1, b2, b3, b4, b5, b6, b7;                            \
            asm volatile("ldmatrix.sync.aligned.m8n8.x4.shared.b16 {%0,%1,%2,%3}, [%4];" \
                         : "=r"(b0), "=r"(b1), "=r"(b2), "=r"(b3) : "r"(ba));   \
            asm volatile("ldmatrix.sync.aligned.m8n8.x4.shared.b16 {%0,%1,%2,%3}, [%4];" \
                         : "=r"(b4), "=r"(b5), "=r"(b6), "=r"(b7) : "r"(ba + 64)); \
            asm volatile("mma.sync.aligned.m16n8k16.row.col.f32.bf16.bf16.f32 " \
                         "{%0,%1,%2,%3}, {%4,%5,%6,%7}, {%8,%9}, {%0,%1,%2,%3};" \
                         : "+f"(acc[nt][0]), "+f"(acc[nt][1]),                  \
                           "+f"(acc[nt][2]), "+f"(acc[nt][3])                   \
                         : "r"(af[0][0]), "r"(af[0][1]), "r"(af[0][2]), "r"(af[0][3]), \
                           "r"(b0), "r"(b1));                                   \
            asm volatile("mma.sync.aligned.m16n8k16.row.col.f32.bf16.bf16.f32 " \
                         "{%0,%1,%2,%3}, {%4,%5,%6,%7}, {%8,%9}, {%0,%1,%2,%3};" \
                         : "+f"(acc[nt][0]), "+f"(acc[nt][1]),                  \
                           "+f"(acc[nt][2]), "+f"(acc[nt][3])                   \
                         : "r"(af[1][0]), "r"(af[1][1]), "r"(af[1][2]), "r"(af[1][3]), \
                           "r"(b2), "r"(b3));                                   \
            asm volatile("mma.sync.aligned.m16n8k16.row.col.f32.bf16.bf16.f32 " \
                         "{%0,%1,%2,%3}, {%4,%5,%6,%7}, {%8,%9}, {%0,%1,%2,%3};" \
                         : "+f"(acc[nt][0]), "+f"(acc[nt][1]),                  \
                           "+f"(acc[nt][2]), "+f"(acc[nt][3])                   \
                         : "r"(af[2][0]), "r"(af[2][1]), "r"(af[2][2]), "r"(af[2][3]), \
                           "r"(b4), "r"(b5));                                   \
            asm volatile("mma.sync.aligned.m16n8k16.row.col.f32.bf16.bf16.f32 " \
                         "{%0,%1,%2,%3}, {%4,%5,%6,%7}, {%8,%9}, {%0,%1,%2,%3};" \
                         : "+f"(acc[nt][0]), "+f"(acc[nt][1]),                  \
                           "+f"(acc[nt][2]), "+f"(acc[nt][3])                   \
                         : "r"(af[3][0]), "r"(af[3][1]), "r"(af[3][2]), "r"(af[3][3]), \
                           "r"(b6), "r"(b7));                                   \
        }                                                                       \
    } while (0)

__device__ __forceinline__ void load_A_and_B0(char* smem, int tid, int k, int nbase) {
    const int4* asrc = (const int4*)&g_v1b[k][nbase][0];
    for (int f = tid; f < 512; f += 256) {
        int r = f >> 3, q = f & 7;
        *(int4*)(smem + OFF_A + r * 144 + q * 16) = asrc[f];
    }
    const int4* bsrc = (const int4*)&g_v2b[k][0][0];
    for (int f = tid; f < 512; f += 256) {
        int r = f >> 3, q = f & 7;
        *(int4*)(smem + OFF_B + r * 144 + q * 16) = bsrc[f];
    }
}

__device__ __forceinline__ void preload_af(uint32_t af[4][4], uint32_t sbase, int rb, int lane) {
    uint32_t abase = sbase + OFF_A + (rb * 16 + (lane & 15)) * 144 + (lane >> 4) * 16;
#pragma unroll
    for (int ks = 0; ks < 4; ks++) {
        asm volatile("ldmatrix.sync.aligned.m8n8.x4.shared.b16 {%0,%1,%2,%3}, [%4];"
                     : "=r"(af[ks][0]), "=r"(af[ks][1]), "=r"(af[ks][2]), "=r"(af[ks][3])
                     : "r"(abase + ks * 32));
    }
}

__device__ __forceinline__ void prefetch_B(char* smem, int tid, int k, int cc1) {
    const int4* src = (const int4*)&g_v2b[k][cc1 * 64][0];
    char* dst = smem + OFF_B + (cc1 & 1) * 9216;
    for (int f = tid; f < 512; f += 256) {
        int r = f >> 3, q = f & 7;
        *(int4*)(dst + r * 144 + q * 16) = src[f];
    }
}

// ---------------------------------------------------------------------------
// Pass 1: HMMA + per-row 32-col sub-chunk maxima.
// grid (half:2, rowtile:128), 256 thr, 2 CTAs/SM.
// ---------------------------------------------------------------------------
__global__ void __launch_bounds__(256, 2) score1_kernel() {
    extern __shared__ char smem[];
    uint32_t sbase = smem_u32(smem);
    int tid = threadIdx.x, wid = tid >> 5, lane = tid & 31;
    int rb = wid & 3, ch = wid >> 2;
    int half = blockIdx.x, rt = blockIdx.y;
    int k = (rt >> 6) * 2 + half;
    int nbase = (rt & 63) * 64;
    int rowg0 = rt * 64;

    load_A_and_B0(smem, tid, k, nbase);
    __syncthreads();

    uint32_t af[4][4];
    preload_af(af, sbase, rb, lane);

    int drow = rb * 16 + (lane >> 2);

    for (int cc = 0; cc < 64; cc++) {
        if (cc + 1 < 64) prefetch_B(smem, tid, k, cc + 1);

        uint32_t bbuf = sbase + OFF_B + (cc & 1) * 9216;
        float acc[4][4];
#pragma unroll
        for (int nt = 0; nt < 4; nt++)
#pragma unroll
            for (int s = 0; s < 4; s++) acc[nt][s] = 0.f;
        MMA_CHUNK4(acc, af, bbuf, ch, lane);

        float mlo = acc[0][0], mhi = acc[0][2];
#pragma unroll
        for (int nt = 0; nt < 4; nt++) {
            mlo = fmaxf(mlo, fmaxf(acc[nt][0], acc[nt][1]));
            mhi = fmaxf(mhi, fmaxf(acc[nt][2], acc[nt][3]));
        }
        mlo = fmaxf(mlo, __shfl_xor_sync(FULLM, mlo, 1));
        mlo = fmaxf(mlo, __shfl_xor_sync(FULLM, mlo, 2));
        mhi = fmaxf(mhi, __shfl_xor_sync(FULLM, mhi, 1));
        mhi = fmaxf(mhi, __shfl_xor_sync(FULLM, mhi, 2));
        if ((lane & 3) == 0) {
            g_cm[rowg0 + drow][half * 128 + cc * 2 + ch]     = mlo;
            g_cm[rowg0 + drow + 8][half * 128 + cc * 2 + ch] = mhi;
        }
        __syncthreads();
    }
}

// ---------------------------------------------------------------------------
// Threshold: T[row] = (20th largest of 256 sub-chunk maxima) - DELTA.
// ---------------------------------------------------------------------------
__global__ void thr_kernel() {
    int w = threadIdx.x >> 5, lane = threadIdx.x & 31;
    int row = blockIdx.x * 8 + w;

    float a[8];
#pragma unroll
    for (int s = 0; s < 8; s++) a[s] = g_cm[row][lane + 32 * s];

    float last = -1e30f;
#pragma unroll
    for (int kk = 0; kk < KTOP; kk++) {
        float bv = a[0];
#pragma unroll
        for (int s = 1; s < 8; s++) bv = fmaxf(bv, a[s]);
#pragma unroll
        for (int off = 16; off > 0; off >>= 1)
            bv = fmaxf(bv, __shfl_xor_sync(FULLM, bv, off));
#pragma unroll
        for (int s = 0; s < 8; s++) a[s] = (a[s] == bv) ? -1e30f : a[s];
        last = bv;
    }
    if (lane == 0) g_T[row] = last - DELTA;
}

// ---------------------------------------------------------------------------
// Pass 2: HMMA + filter-append values > T into per-row FIFOs.
// smem: A+B(27648) + fv 64*48*4 @27648 + fc @39936 + cnt @46080 = 46336.
// ---------------------------------------------------------------------------
#define OFF_FV 27648
#define OFF_FC 39936
#define OFF_CN 46080
#define SM2_TOTAL 46336

__global__ void __launch_bounds__(256, 2) score2_kernel() {
    extern __shared__ char smem[];
    uint32_t sbase = smem_u32(smem);
    int tid = threadIdx.x, wid = tid >> 5, lane = tid & 31;
    int rb = wid & 3, ch = wid >> 2;
    int half = blockIdx.x, rt = blockIdx.y;
    int k = (rt >> 6) * 2 + half;
    int nbase = (rt & 63) * 64;
    int rowg0 = rt * 64;

    float* fv = (float*)(smem + OFF_FV);
    unsigned short* fc = (unsigned short*)(smem + OFF_FC);
    int* cnt = (int*)(smem + OFF_CN);
    if (tid < 64) cnt[tid] = 0;

    load_A_and_B0(smem, tid, k, nbase);
    __syncthreads();

    uint32_t af[4][4];
    preload_af(af, sbase, rb, lane);

    int drow = rb * 16 + (lane >> 2);
    int dcol = (lane & 3) * 2;
    float Tlo = g_T[rowg0 + drow];
    float Thi = g_T[rowg0 + drow + 8];
    int cbase = half * 4096;

    for (int cc = 0; cc < 64; cc++) {
        if (cc + 1 < 64) prefetch_B(smem, tid, k, cc + 1);

        uint32_t bbuf = sbase + OFF_B + (cc & 1) * 9216;
        float acc[4][4];
#pragma unroll
        for (int nt = 0; nt < 4; nt++)
#pragma unroll
            for (int s = 0; s < 4; s++) acc[nt][s] = 0.f;
        MMA_CHUNK4(acc, af, bbuf, ch, lane);

#pragma unroll
        for (int nt = 0; nt < 4; nt++) {
            int colb = cc * 64 + ch * 32 + nt * 8 + dcol;
            if (acc[nt][0] > Tlo) {
                int p = atomicAdd(&cnt[drow], 1);
                if (p < CAND) { fv[drow * CAND + p] = acc[nt][0];
                                fc[drow * CAND + p] = (unsigned short)(cbase + colb); }
            }
            if (acc[nt][1] > Tlo) {
                int p = atomicAdd(&cnt[drow], 1);
                if (p < CAND) { fv[drow * CAND + p] = acc[nt][1];
                                fc[drow * CAND + p] = (unsigned short)(cbase + colb + 1); }
            }
            if (acc[nt][2] > Thi) {
                int p = atomicAdd(&cnt[drow + 8], 1);
                if (p < CAND) { fv[(drow + 8) * CAND + p] = acc[nt][2];
                                fc[(drow + 8) * CAND + p] = (unsigned short)(cbase + colb); }
            }
            if (acc[nt][3] > Thi) {
                int p = atomicAdd(&cnt[drow + 8], 1);
                if (p < CAND) { fv[(drow + 8) * CAND + p] = acc[nt][3];
                                fc[(drow + 8) * CAND + p] = (unsigned short)(cbase + colb + 1); }
            }
        }
        __syncthreads();
    }

    for (int t = tid; t < 64 * CAND; t += 256) {
        int r = t / CAND, i = t % CAND;
        int n = min(cnt[r], CAND);
        g_cval[rowg0 + r][half * CAND + i] = (i < n) ? fv[t] : -1e30f;
        g_ccol[rowg0 + r][half * CAND + i] = fc[t];
    }
}

// ---------------------------------------------------------------------------
// Merge (+fused output zeroing): block = 8 rows.
// ---------------------------------------------------------------------------
__global__ void merge_rescore_kernel(float* __restrict__ out) {
    __shared__ float sv1[8][2][64];
    int tid = threadIdx.x;
    int w = tid >> 5, lane = tid & 31;
    int row0 = blockIdx.x * 8;
    int row = row0 + w;
    int mod_i = row >> 12, rloc = row & 4095;

    {
        float4* ob = (float4*)(out + (size_t)row0 * NROWS);
        for (int t = tid; t < 8 * NROWS / 4; t += 256)
            ob[t] = make_float4(0.f, 0.f, 0.f, 0.f);
    }

    for (int t = lane; t < 128; t += 32) {
        int h = t >> 6, d = t & 63;
        sv1[w][h][d] = g_v1[mod_i * 2 + h][rloc][d];
    }
    __syncthreads();

    float rv[3]; int gc[3];
#pragma unroll
    for (int s = 0; s < 3; s++) {
        int idx = lane * 3 + s;
        float bval = g_cval[row][idx];
        int   col  = (int)g_ccol[row][idx];
        gc[s] = col;
        if (bval > -1e29f) {
            int h = col >> 12, cl = col & 4095;
            const float4* v2c = (const float4*)&g_v2[mod_i * 2 + h][cl][0];
            const float4* v1c = (const float4*)&sv1[w][h][0];
            float acc = 0.f;
#pragma unroll
            for (int dd = 0; dd < 16; dd++) {
                float4 x = v1c[dd], y = v2c[dd];
                acc += x.x * y.x + x.y * y.y + x.z * y.z + x.w * y.w;
            }
            rv[s] = acc;
        } else {
            rv[s] = -1e30f;
        }
    }

#pragma unroll
    for (int kk = 0; kk < KTOP; kk++) {
        float bv = rv[0]; int bs = 0;
        if (rv[1] > bv) { bv = rv[1]; bs = 1; }
        if (rv[2] > bv) { bv = rv[2]; bs = 2; }
        int bc = gc[bs];
        int bi = lane * 4 + bs;
#pragma unroll
        for (int off = 16; off > 0; off >>= 1) {
            float ov = __shfl_xor_sync(FULLM, bv, off);
            int   oc = __shfl_xor_sync(FULLM, bc, off);
            int   oi = __shfl_xor_sync(FULLM, bi, off);
            if (ov > bv || (ov == bv && oi < bi)) { bv = ov; bc = oc; bi = oi; }
        }
        if (lane == (bi >> 2)) rv[bi & 3] = -1e30f;
        if (lane == kk) {
            float t = (bv > 0.f) ? tanhf(3.0f * bv) : 0.f;
            out[(size_t)row * NROWS + bc] = t;
        }
    }
}

// ---------------------------------------------------------------------------
extern "C" void kernel_launch(void* const* d_in, const int* in_sizes, int n_in,
                              void* d_out, int out_size) {
    const float* emb1 = (const float*)d_in[1];
    const float* emb2 = (const float*)d_in[2];
    const float* w1   = (const float*)d_in[3];
    const float* w2   = (const float*)d_in[4];
    const float* b1   = (const float*)d_in[5];
    const float* b2   = (const float*)d_in[6];
    float* out = (float*)d_out;

    cudaFuncSetAttribute(score1_kernel,
                         cudaFuncAttributeMaxDynamicSharedMemorySize, SM_AB);
    cudaFuncSetAttribute(score2_kernel,
                         cudaFuncAttributeMaxDynamicSharedMemorySize, SM2_TOTAL);

    compute_v_kernel<<<dim3(64, NMAT, 2), 256>>>(emb1, emb2, w1, w2, b1, b2);
    score1_kernel<<<dim3(2, 128), 256, SM_AB>>>();
    thr_kernel<<<NROWS / 8, 256>>>();
    score2_kernel<<<dim3(2, 128), 256, SM2_TOTAL>>>();
    merge_rescore_kernel<<<NROWS / 8, 256>>>(out);
}

// round 11
// speedup vs baseline: 1.1771x; 1.1771x over previous
#include <cuda_runtime.h>
#include <cuda_bf16.h>
#include <math.h>
#include <stdint.h>

#define NMAT 4
#define NSUB 4096
#define DIM 64
#define KTOP 20
#define NROWS 8192
#define DELTA 0.008f
#define FULLM 0xffffffffu
#define CAND 48            // candidates per half-row

// device global scratch (no allocation allowed)
__device__ float g_v1[NMAT][NSUB][DIM];
__device__ float g_v2[NMAT][NSUB][DIM];
__device__ __nv_bfloat16 g_v1b[NMAT][NSUB][DIM];
__device__ __nv_bfloat16 g_v2b[NMAT][NSUB][DIM];
__device__ float          g_cm[NROWS][256];       // per-row 32-col sub-chunk maxima
__device__ float          g_T[NROWS];             // per-row filter threshold
__device__ float          g_cval[NROWS][2 * CAND];
__device__ unsigned short g_ccol[NROWS][2 * CAND];

__device__ __forceinline__ uint32_t smem_u32(const void* p) {
    uint32_t a;
    asm("{ .reg .u64 t; cvta.to.shared.u64 t, %1; cvt.u32.u64 %0, t; }" : "=r"(a) : "l"(p));
    return a;
}

// ---------------------------------------------------------------------------
// v = emb @ w + b (fp32) + bf16 copy
// ---------------------------------------------------------------------------
__global__ void compute_v_kernel(const float* __restrict__ emb1,
                                 const float* __restrict__ emb2,
                                 const float* __restrict__ w1,
                                 const float* __restrict__ w2,
                                 const float* __restrict__ b1,
                                 const float* __restrict__ b2) {
    int which = blockIdx.z;
    int k = blockIdx.y;
    int tile = blockIdx.x;
    const float* emb = which ? emb2 : emb1;
    const float* w   = which ? w2   : w1;
    const float* b   = which ? b2   : b1;
    float* vout            = which ? &g_v2[0][0][0]  : &g_v1[0][0][0];
    __nv_bfloat16* voutb   = which ? &g_v2b[0][0][0] : &g_v1b[0][0][0];

    __shared__ float semb[64 * 65];
    __shared__ float sw[64 * 64];
    __shared__ float sb[64];

    int tid = threadIdx.x;
    for (int t = tid; t < 4096; t += 256) {
        int r = t >> 6, e = t & 63;
        semb[r * 65 + e] = emb[(size_t)(k * NSUB + tile * 64 + r) * 64 + e];
        sw[t] = w[k * 4096 + t];
    }
    if (tid < 64) sb[tid] = b[k * 64 + tid];
    __syncthreads();

    int nl = tid & 63, q = tid >> 6;
    float acc[16];
#pragma unroll
    for (int d = 0; d < 16; d++) acc[d] = 0.f;

#pragma unroll 4
    for (int e = 0; e < 64; e++) {
        float a = semb[nl * 65 + e];
#pragma unroll
        for (int jj = 0; jj < 4; jj++) {
            float4 wv = *(const float4*)&sw[e * 64 + q * 16 + jj * 4];
            acc[jj * 4 + 0] += a * wv.x;
            acc[jj * 4 + 1] += a * wv.y;
            acc[jj * 4 + 2] += a * wv.z;
            acc[jj * 4 + 3] += a * wv.w;
        }
    }

    size_t rowoff = (size_t)(k * NSUB + tile * 64 + nl) * 64;
    float* orow = vout + rowoff;
    __nv_bfloat16* orowb = voutb + rowoff;
#pragma unroll
    for (int dd = 0; dd < 16; dd++) {
        int d = q * 16 + dd;
        float v = acc[dd] + sb[d];
        orow[d]  = v;
        orowb[d] = __float2bfloat16(v);
    }
}

// ---------------------------------------------------------------------------
// HMMA plumbing. 512 threads, 128-row tile: warp w = (rowband rb = w&7) x
// (colhalf ch = w>>3). Warp computes 16 rows x 32 cols per 64-col chunk.
// B: 4-stage cp.async ring, 3-deep prefetch. B frags via ldmatrix.x4.
// ---------------------------------------------------------------------------
#define OFF_A  0
#define OFF_B  18432
#define SM_AB  55296            // A(18432) + 4 B buffers(4x9216)

#define MMA_CHUNK4(acc, af, bbuf, ch, lane)                                     \
    do {                                                                        \
        uint32_t baddr0 = (bbuf) + ((ch) * 32 + ((lane) & 7)) * 144             \
                          + ((lane) >> 3) * 16;                                 \
        _Pragma("unroll")                                                       \
        for (int nt = 0; nt < 4; nt++) {                                        \
            uint32_t ba = baddr0 + nt * 8 * 144;                                \
            uint32_t b0, b1, b2, b3, b4, b5, b6, b7;                            \
            asm volatile("ldmatrix.sync.aligned.m8n8.x4.shared.b16 {%0,%1,%2,%3}, [%4];" \
                         : "=r"(b0), "=r"(b1), "=r"(b2), "=r"(b3) : "r"(ba));   \
            asm volatile("ldmatrix.sync.aligned.m8n8.x4.shared.b16 {%0,%1,%2,%3}, [%4];" \
                         : "=r"(b4), "=r"(b5), "=r"(b6), "=r"(b7) : "r"(ba + 64)); \
            asm volatile("mma.sync.aligned.m16n8k16.row.col.f32.bf16.bf16.f32 " \
                         "{%0,%1,%2,%3}, {%4,%5,%6,%7}, {%8,%9}, {%0,%1,%2,%3};" \
                         : "+f"(acc[nt][0]), "+f"(acc[nt][1]),                  \
                           "+f"(acc[nt][2]), "+f"(acc[nt][3])                   \
                         : "r"(af[0][0]), "r"(af[0][1]), "r"(af[0][2]), "r"(af[0][3]), \
                           "r"(b0), "r"(b1));                                   \
            asm volatile("mma.sync.aligned.m16n8k16.row.col.f32.bf16.bf16.f32 " \
                         "{%0,%1,%2,%3}, {%4,%5,%6,%7}, {%8,%9}, {%0,%1,%2,%3};" \
                         : "+f"(acc[nt][0]), "+f"(acc[nt][1]),                  \
                           "+f"(acc[nt][2]), "+f"(acc[nt][3])                   \
                         : "r"(af[1][0]), "r"(af[1][1]), "r"(af[1][2]), "r"(af[1][3]), \
                           "r"(b2), "r"(b3));                                   \
            asm volatile("mma.sync.aligned.m16n8k16.row.col.f32.bf16.bf16.f32 " \
                         "{%0,%1,%2,%3}, {%4,%5,%6,%7}, {%8,%9}, {%0,%1,%2,%3};" \
                         : "+f"(acc[nt][0]), "+f"(acc[nt][1]),                  \
                           "+f"(acc[nt][2]), "+f"(acc[nt][3])                   \
                         : "r"(af[2][0]), "r"(af[2][1]), "r"(af[2][2]), "r"(af[2][3]), \
                           "r"(b4), "r"(b5));                                   \
            asm volatile("mma.sync.aligned.m16n8k16.row.col.f32.bf16.bf16.f32 " \
                         "{%0,%1,%2,%3}, {%4,%5,%6,%7}, {%8,%9}, {%0,%1,%2,%3};" \
                         : "+f"(acc[nt][0]), "+f"(acc[nt][1]),                  \
                           "+f"(acc[nt][2]), "+f"(acc[nt][3])                   \
                         : "r"(af[3][0]), "r"(af[3][1]), "r"(af[3][2]), "r"(af[3][3]), \
                           "r"(b6), "r"(b7));                                   \
        }                                                                       \
    } while (0)

__device__ __forceinline__ void load_A(char* smem, int tid, int k, int nbase) {
    const int4* asrc = (const int4*)&g_v1b[k][nbase][0];
    for (int f = tid; f < 1024; f += 512) {
        int r = f >> 3, q = f & 7;
        *(int4*)(smem + OFF_A + r * 144 + q * 16) = asrc[f];
    }
}

// one 16B cp.async per thread = 8KB B chunk; one commit group per chunk
__device__ __forceinline__ void cp_async_B(uint32_t sbase, int tid, int k, int cc) {
    const int4* src = (const int4*)&g_v2b[k][cc * 64][0] + tid;
    int r = tid >> 3, q = tid & 7;
    uint32_t dst = sbase + OFF_B + (cc & 3) * 9216 + r * 144 + q * 16;
    asm volatile("cp.async.cg.shared.global [%0], [%1], 16;" :: "r"(dst), "l"(src));
    asm volatile("cp.async.commit_group;");
}

__device__ __forceinline__ void preload_af(uint32_t af[4][4], uint32_t sbase, int rb, int lane) {
    uint32_t abase = sbase + OFF_A + (rb * 16 + (lane & 15)) * 144 + (lane >> 4) * 16;
#pragma unroll
    for (int ks = 0; ks < 4; ks++) {
        asm volatile("ldmatrix.sync.aligned.m8n8.x4.shared.b16 {%0,%1,%2,%3}, [%4];"
                     : "=r"(af[ks][0]), "=r"(af[ks][1]), "=r"(af[ks][2]), "=r"(af[ks][3])
                     : "r"(abase + ks * 32));
    }
}

// ---------------------------------------------------------------------------
// Pass 1: HMMA + per-row 32-col sub-chunk maxima. grid (half:2, rowtile:64).
// ---------------------------------------------------------------------------
__global__ void __launch_bounds__(512, 1) score1_kernel() {
    extern __shared__ char smem[];
    uint32_t sbase = smem_u32(smem);
    int tid = threadIdx.x, wid = tid >> 5, lane = tid & 31;
    int rb = wid & 7, ch = wid >> 3;
    int half = blockIdx.x, rt = blockIdx.y;
    int k = (rt >> 5) * 2 + half;
    int nbase = (rt & 31) * 128;
    int rowg0 = rt * 128;

    load_A(smem, tid, k, nbase);
    cp_async_B(sbase, tid, k, 0);
    cp_async_B(sbase, tid, k, 1);
    cp_async_B(sbase, tid, k, 2);
    __syncthreads();

    uint32_t af[4][4];
    preload_af(af, sbase, rb, lane);

    int drow = rb * 16 + (lane >> 2);

    for (int cc = 0; cc < 64; cc++) {
        asm volatile("cp.async.wait_group 2;");
        __syncthreads();
        if (cc + 3 < 64) cp_async_B(sbase, tid, k, cc + 3);

        uint32_t bbuf = sbase + OFF_B + (cc & 3) * 9216;
        float acc[4][4];
#pragma unroll
        for (int nt = 0; nt < 4; nt++)
#pragma unroll
            for (int s = 0; s < 4; s++) acc[nt][s] = 0.f;
        MMA_CHUNK4(acc, af, bbuf, ch, lane);

        float mlo = acc[0][0], mhi = acc[0][2];
#pragma unroll
        for (int nt = 0; nt < 4; nt++) {
            mlo = fmaxf(mlo, fmaxf(acc[nt][0], acc[nt][1]));
            mhi = fmaxf(mhi, fmaxf(acc[nt][2], acc[nt][3]));
        }
        mlo = fmaxf(mlo, __shfl_xor_sync(FULLM, mlo, 1));
        mlo = fmaxf(mlo, __shfl_xor_sync(FULLM, mlo, 2));
        mhi = fmaxf(mhi, __shfl_xor_sync(FULLM, mhi, 1));
        mhi = fmaxf(mhi, __shfl_xor_sync(FULLM, mhi, 2));
        if ((lane & 3) == 0) {
            g_cm[rowg0 + drow][half * 128 + cc * 2 + ch]     = mlo;
            g_cm[rowg0 + drow + 8][half * 128 + cc * 2 + ch] = mhi;
        }
    }
}

// ---------------------------------------------------------------------------
// Threshold: T[row] = (20th largest of 256 sub-chunk maxima) - DELTA.
// ---------------------------------------------------------------------------
__global__ void thr_kernel() {
    int w = threadIdx.x >> 5, lane = threadIdx.x & 31;
    int row = blockIdx.x * 8 + w;

    float a[8];
#pragma unroll
    for (int s = 0; s < 8; s++) a[s] = g_cm[row][lane + 32 * s];

    float last = -1e30f;
#pragma unroll
    for (int kk = 0; kk < KTOP; kk++) {
        float bv = a[0];
#pragma unroll
        for (int s = 1; s < 8; s++) bv = fmaxf(bv, a[s]);
#pragma unroll
        for (int off = 16; off > 0; off >>= 1)
            bv = fmaxf(bv, __shfl_xor_sync(FULLM, bv, off));
#pragma unroll
        for (int s = 0; s < 8; s++) a[s] = (a[s] == bv) ? -1e30f : a[s];
        last = bv;
    }
    if (lane == 0) g_T[row] = last - DELTA;
}

// ---------------------------------------------------------------------------
// Pass 2: HMMA + filter-append values > T into per-row FIFOs.
// smem: A+4B(55296) + fv 128*48*4 @55296 + fc @79872 + cnt @92160 = 92672.
// ---------------------------------------------------------------------------
#define OFF_FV 55296
#define OFF_FC 79872
#define OFF_CN 92160
#define SM2_TOTAL 92672

__global__ void __launch_bounds__(512, 1) score2_kernel() {
    extern __shared__ char smem[];
    uint32_t sbase = smem_u32(smem);
    int tid = threadIdx.x, wid = tid >> 5, lane = tid & 31;
    int rb = wid & 7, ch = wid >> 3;
    int half = blockIdx.x, rt = blockIdx.y;
    int k = (rt >> 5) * 2 + half;
    int nbase = (rt & 31) * 128;
    int rowg0 = rt * 128;

    float* fv = (float*)(smem + OFF_FV);
    unsigned short* fc = (unsigned short*)(smem + OFF_FC);
    int* cnt = (int*)(smem + OFF_CN);
    if (tid < 128) cnt[tid] = 0;

    load_A(smem, tid, k, nbase);
    cp_async_B(sbase, tid, k, 0);
    cp_async_B(sbase, tid, k, 1);
    cp_async_B(sbase, tid, k, 2);
    __syncthreads();

    uint32_t af[4][4];
    preload_af(af, sbase, rb, lane);

    int drow = rb * 16 + (lane >> 2);
    int dcol = (lane & 3) * 2;
    float Tlo = g_T[rowg0 + drow];
    float Thi = g_T[rowg0 + drow + 8];
    int cbase = half * 4096;

    for (int cc = 0; cc < 64; cc++) {
        asm volatile("cp.async.wait_group 2;");
        __syncthreads();
        if (cc + 3 < 64) cp_async_B(sbase, tid, k, cc + 3);

        uint32_t bbuf = sbase + OFF_B + (cc & 3) * 9216;
        float acc[4][4];
#pragma unroll
        for (int nt = 0; nt < 4; nt++)
#pragma unroll
            for (int s = 0; s < 4; s++) acc[nt][s] = 0.f;
        MMA_CHUNK4(acc, af, bbuf, ch, lane);

#pragma unroll
        for (int nt = 0; nt < 4; nt++) {
            int colb = cc * 64 + ch * 32 + nt * 8 + dcol;
            if (acc[nt][0] > Tlo) {
                int p = atomicAdd(&cnt[drow], 1);
                if (p < CAND) { fv[drow * CAND + p] = acc[nt][0];
                                fc[drow * CAND + p] = (unsigned short)(cbase + colb); }
            }
            if (acc[nt][1] > Tlo) {
                int p = atomicAdd(&cnt[drow], 1);
                if (p < CAND) { fv[drow * CAND + p] = acc[nt][1];
                                fc[drow * CAND + p] = (unsigned short)(cbase + colb + 1); }
            }
            if (acc[nt][2] > Thi) {
                int p = atomicAdd(&cnt[drow + 8], 1);
                if (p < CAND) { fv[(drow + 8) * CAND + p] = acc[nt][2];
                                fc[(drow + 8) * CAND + p] = (unsigned short)(cbase + colb); }
            }
            if (acc[nt][3] > Thi) {
                int p = atomicAdd(&cnt[drow + 8], 1);
                if (p < CAND) { fv[(drow + 8) * CAND + p] = acc[nt][3];
                                fc[(drow + 8) * CAND + p] = (unsigned short)(cbase + colb + 1); }
            }
        }
    }
    __syncthreads();

    for (int t = tid; t < 128 * CAND; t += 512) {
        int r = t / CAND, i = t % CAND;
        int n = min(cnt[r], CAND);
        g_cval[rowg0 + r][half * CAND + i] = (i < n) ? fv[t] : -1e30f;
        g_ccol[rowg0 + r][half * CAND + i] = fc[t];
    }
}

// ---------------------------------------------------------------------------
// Merge (+fused output zeroing): block = 8 rows.
// ---------------------------------------------------------------------------
__global__ void merge_rescore_kernel(float* __restrict__ out) {
    __shared__ float sv1[8][2][64];
    int tid = threadIdx.x;
    int w = tid >> 5, lane = tid & 31;
    int row0 = blockIdx.x * 8;
    int row = row0 + w;
    int mod_i = row >> 12, rloc = row & 4095;

    {
        float4* ob = (float4*)(out + (size_t)row0 * NROWS);
        for (int t = tid; t < 8 * NROWS / 4; t += 256)
            ob[t] = make_float4(0.f, 0.f, 0.f, 0.f);
    }

    for (int t = lane; t < 128; t += 32) {
        int h = t >> 6, d = t & 63;
        sv1[w][h][d] = g_v1[mod_i * 2 + h][rloc][d];
    }
    __syncthreads();

    float rv[3]; int gc[3];
#pragma unroll
    for (int s = 0; s < 3; s++) {
        int idx = lane * 3 + s;
        float bval = g_cval[row][idx];
        int   col  = (int)g_ccol[row][idx];
        gc[s] = col;
        if (bval > -1e29f) {
            int h = col >> 12, cl = col & 4095;
            const float4* v2c = (const float4*)&g_v2[mod_i * 2 + h][cl][0];
            const float4* v1c = (const float4*)&sv1[w][h][0];
            float acc = 0.f;
#pragma unroll
            for (int dd = 0; dd < 16; dd++) {
                float4 x = v1c[dd], y = v2c[dd];
                acc += x.x * y.x + x.y * y.y + x.z * y.z + x.w * y.w;
            }
            rv[s] = acc;
        } else {
            rv[s] = -1e30f;
        }
    }

#pragma unroll
    for (int kk = 0; kk < KTOP; kk++) {
        float bv = rv[0]; int bs = 0;
        if (rv[1] > bv) { bv = rv[1]; bs = 1; }
        if (rv[2] > bv) { bv = rv[2]; bs = 2; }
        int bc = gc[bs];
        int bi = lane * 4 + bs;
#pragma unroll
        for (int off = 16; off > 0; off >>= 1) {
            float ov = __shfl_xor_sync(FULLM, bv, off);
            int   oc = __shfl_xor_sync(FULLM, bc, off);
            int   oi = __shfl_xor_sync(FULLM, bi, off);
            if (ov > bv || (ov == bv && oi < bi)) { bv = ov; bc = oc; bi = oi; }
        }
        if (lane == (bi >> 2)) rv[bi & 3] = -1e30f;
        if (lane == kk) {
            float t = (bv > 0.f) ? tanhf(3.0f * bv) : 0.f;
            out[(size_t)row * NROWS + bc] = t;
        }
    }
}

// ---------------------------------------------------------------------------
extern "C" void kernel_launch(void* const* d_in, const int* in_sizes, int n_in,
                              void* d_out, int out_size) {
    const float* emb1 = (const float*)d_in[1];
    const float* emb2 = (const float*)d_in[2];
    const float* w1   = (const float*)d_in[3];
    const float* w2   = (const float*)d_in[4];
    const float* b1   = (const float*)d_in[5];
    const float* b2   = (const float*)d_in[6];
    float* out = (float*)d_out;

    cudaFuncSetAttribute(score1_kernel,
                         cudaFuncAttributeMaxDynamicSharedMemorySize, SM_AB);
    cudaFuncSetAttribute(score2_kernel,
                         cudaFuncAttributeMaxDynamicSharedMemorySize, SM2_TOTAL);

    compute_v_kernel<<<dim3(64, NMAT, 2), 256>>>(emb1, emb2, w1, w2, b1, b2);
    score1_kernel<<<dim3(2, 64), 512, SM_AB>>>();
    thr_kernel<<<NROWS / 8, 256>>>();
    score2_kernel<<<dim3(2, 64), 512, SM2_TOTAL>>>();
    merge_rescore_kernel<<<NROWS / 8, 256>>>(out);
}